// round 16
// baseline (speedup 1.0000x reference)
#include <cuda_runtime.h>
#include <cuda_fp16.h>
#include <math.h>
#include <float.h>

#define NN 100000
#define F 128          // HEADS*NHID
#define EMAX 1700000   // 1.6M edges + 100k self loops

// ---------------- scratch (device globals; no allocation allowed) ----------------
__device__ __half g_h16[(size_t)NN * F];   // h = x @ W, fp16 (gather payload)
__device__ __half g_out16[(size_t)NN * F]; // activated layer output, fp16
__device__ float g_als[NN * 4];            // alpha logits (src side), per head
__device__ float g_ald[NN * 4];            // alpha logits (dst side), per head
__device__ __half g_wt16[3][F * F];        // W^T in fp16, per layer

// CSR build scratch (g_deg is zero at module load; csr_scanB re-zeros it each run)
__device__ int g_deg[NN];                  // real-edge degree (self-loop added in scanB)
__device__ int g_rowptr[NN + 1];
__device__ int g_wptr[NN];
__device__ int g_bsum[128];
__device__ int g_csr_src[EMAX];

// ---------------- helpers ----------------
__device__ __forceinline__ float lrelu(float v) { return v > 0.f ? v : 0.2f * v; }

__device__ __forceinline__ void mma16816(float* d, const unsigned* a, const unsigned* b)
{
    asm volatile(
        "mma.sync.aligned.m16n8k16.row.col.f32.f16.f16.f32 "
        "{%0,%1,%2,%3}, {%4,%5,%6,%7}, {%8,%9}, {%0,%1,%2,%3};"
        : "+f"(d[0]), "+f"(d[1]), "+f"(d[2]), "+f"(d[3])
        : "r"(a[0]), "r"(a[1]), "r"(a[2]), "r"(a[3]), "r"(b[0]), "r"(b[1]));
}

// ---------------- launch 1: fused W-transpose-to-fp16 + edge histogram ----------
__global__ __launch_bounds__(256) void csr_hist_wconv(
    const int* __restrict__ ei, int E, int hblocks,
    const float* __restrict__ W0, const float* __restrict__ W1,
    const float* __restrict__ W2)
{
    int b = blockIdx.x;
    if (b < hblocks) {
        int i = (b * 256 + threadIdx.x) * 4;
        if (((E & 3) == 0) && i + 3 < E) {
            int4 d4 = *(const int4*)(ei + E + i);
            atomicAdd(&g_deg[d4.x], 1);
            atomicAdd(&g_deg[d4.y], 1);
            atomicAdd(&g_deg[d4.z], 1);
            atomicAdd(&g_deg[d4.w], 1);
        } else {
#pragma unroll
            for (int k = 0; k < 4; k++)
                if (i + k < E) atomicAdd(&g_deg[ei[E + i + k]], 1);
        }
    } else {
        int i = (b - hblocks) * 256 + threadIdx.x;      // 0 .. 3*16384-1
        if (i >= 3 * F * F) return;
        int l = i >> 14;
        int r = i & (F * F - 1);
        int n = r >> 7;
        int k = r & 127;
        const float* W = (l == 0) ? W0 : ((l == 1) ? W1 : W2);
        g_wt16[l][n * F + k] = __float2half(W[k * F + n]);
    }
}

// ---------------- launch 2: per-1024-block degree sums ----------------
__global__ __launch_bounds__(1024) void csr_scanA(int n)
{
    __shared__ int sm[32];
    int i = blockIdx.x * 1024 + threadIdx.x;
    int v = (i < n) ? (g_deg[i] + 1) : 0;     // +1: self loop
#pragma unroll
    for (int off = 16; off; off >>= 1) v += __shfl_xor_sync(0xffffffffu, v, off);
    if ((threadIdx.x & 31) == 0) sm[threadIdx.x >> 5] = v;
    __syncthreads();
    if (threadIdx.x < 32) {
        int w = sm[threadIdx.x];
#pragma unroll
        for (int off = 16; off; off >>= 1) w += __shfl_xor_sync(0xffffffffu, w, off);
        if (threadIdx.x == 0) g_bsum[blockIdx.x] = w;
    }
}

// ---------------- launch 3: exclusive scan -> rowptr/wptr; resets g_deg ---------
__global__ __launch_bounds__(1024) void csr_scanB(int n, int EN)
{
    __shared__ int sm[1024];
    __shared__ int boff;
    int i = blockIdx.x * 1024 + threadIdx.x;
    int d = (i < n) ? (g_deg[i] + 1) : 0;     // +1: self loop
    if (threadIdx.x < 32) {
        int o = 0;
        for (int b = (int)threadIdx.x; b < (int)blockIdx.x; b += 32) o += g_bsum[b];
#pragma unroll
        for (int off = 16; off; off >>= 1) o += __shfl_xor_sync(0xffffffffu, o, off);
        if (threadIdx.x == 0) boff = o;
    }
    sm[threadIdx.x] = d;
    __syncthreads();
#pragma unroll
    for (int off = 1; off < 1024; off <<= 1) {
        int t = (threadIdx.x >= off) ? sm[threadIdx.x - off] : 0;
        __syncthreads();
        sm[threadIdx.x] += t;
        __syncthreads();
    }
    if (i < n) {
        int ex = boff + sm[threadIdx.x] - d;
        g_rowptr[i] = ex;
        g_wptr[i] = ex;
        g_deg[i] = 0;                       // reset for the next replay
        if (i == n - 1) g_rowptr[n] = ex + d;
    }
}

// ---------------- launch 5: scatter (4 real edges/thread + self-loop range) -----
__global__ __launch_bounds__(256) void csr_scatter(const int* __restrict__ ei,
                                                   int E, int sblocks)
{
    int b = blockIdx.x;
    if (b < sblocks) {
        int i = (b * 256 + threadIdx.x) * 4;
        if (((E & 3) == 0) && i + 3 < E) {
            int4 s4 = *(const int4*)(ei + i);
            int4 d4 = *(const int4*)(ei + E + i);
            int p0 = atomicAdd(&g_wptr[d4.x], 1);
            int p1 = atomicAdd(&g_wptr[d4.y], 1);
            int p2 = atomicAdd(&g_wptr[d4.z], 1);
            int p3 = atomicAdd(&g_wptr[d4.w], 1);
            g_csr_src[p0] = s4.x;
            g_csr_src[p1] = s4.y;
            g_csr_src[p2] = s4.z;
            g_csr_src[p3] = s4.w;
        } else {
#pragma unroll
            for (int k = 0; k < 4; k++)
                if (i + k < E) {
                    int s = ei[i + k], d = ei[E + i + k];
                    int pos = atomicAdd(&g_wptr[d], 1);
                    g_csr_src[pos] = s;
                }
        }
    } else {
        int i = (b - sblocks) * 256 + threadIdx.x;   // self loops
        if (i < NN) {
            int pos = atomicAdd(&g_wptr[i], 1);
            g_csr_src[pos] = i;
        }
    }
}

// ---------------- X-tile loaders (fp32 layer0 / fp16 layers 1-2), 256 threads ----
#define XPAD 136   // 128 + 8 halves padding
__device__ __forceinline__ void load_xtile(
    const float* __restrict__ X, __half* xs, int tid, int row0, int nrows)
{
#pragma unroll
    for (int i = 0; i < 16; i++) {
        int f = tid + i * 256;               // float4 index: 128 rows x 32
        int r = f >> 5, c4 = (f & 31) << 2;
        float4 v = make_float4(0.f, 0.f, 0.f, 0.f);
        if (row0 + r < nrows) v = *(const float4*)(X + (size_t)(row0 + r) * F + c4);
        __half2 p0 = __floats2half2_rn(v.x, v.y);
        __half2 p1 = __floats2half2_rn(v.z, v.w);
        uint2 u;
        u.x = *(unsigned*)&p0; u.y = *(unsigned*)&p1;
        *(uint2*)(xs + r * XPAD + c4) = u;
    }
}

__device__ __forceinline__ void load_xtile(
    const __half* __restrict__ X, __half* xs, int tid, int row0, int nrows)
{
#pragma unroll
    for (int i = 0; i < 8; i++) {
        int f = tid + i * 256;               // uint4 index: 128 rows x 16
        int r = f >> 4, c = (f & 15) << 3;
        uint4 u = make_uint4(0u, 0u, 0u, 0u);
        if (row0 + r < nrows) u = *(const uint4*)(X + (size_t)(row0 + r) * F + c);
        *(uint4*)(xs + r * XPAD + c) = u;
    }
}

// ---------------- launch 4: HMMA GEMM + fused attention-logit epilogue ----------
// R14 configuration (measured 27.9us): 128x128 tile, 256 threads = 4(m) x 2(n).
template <typename T>
__global__ __launch_bounds__(256) void gemm_mma(
    const T* __restrict__ X, const __half* __restrict__ WT,
    const float* __restrict__ a_src, const float* __restrict__ a_dst, int nrows)
{
    extern __shared__ __half sh[];
    __half* xs = sh;                 // [128][XPAD]  row-major (m,k)
    __half* ws = sh + 128 * XPAD;    // [128][XPAD]  n-major  (n,k)

    const int tid = threadIdx.x;
    const int warp = tid >> 5, lane = tid & 31;
    const int g = lane >> 2, tg = lane & 3;
    const int wm = warp & 3, wn = warp >> 2;     // 4 m-warps x 2 n-warps
    const int row0 = blockIdx.x * 128;

    load_xtile(X, xs, tid, row0, nrows);
#pragma unroll
    for (int i = 0; i < 8; i++) {
        int f = tid + i * 256;               // uint4 index: 128 rows x 16
        int n = f >> 4, kw = (f & 15) << 3;
        *(uint4*)(ws + n * XPAD + kw) = *(const uint4*)(WT + n * F + kw);
    }
    __syncthreads();

    float acc[2][8][4];
#pragma unroll
    for (int mt = 0; mt < 2; mt++)
#pragma unroll
        for (int nt = 0; nt < 8; nt++)
#pragma unroll
            for (int c = 0; c < 4; c++) acc[mt][nt][c] = 0.f;

    const __half* xw = xs + (wm * 32) * XPAD;
    const __half* ww = ws + (wn * 64) * XPAD;

#pragma unroll
    for (int kt = 0; kt < 8; kt++) {
        const int kb = kt * 16;
        unsigned a[2][4], b[8][2];
#pragma unroll
        for (int mt = 0; mt < 2; mt++) {
            const __half* base = xw + (mt * 16) * XPAD + kb + tg * 2;
            a[mt][0] = *(const unsigned*)(base + g * XPAD);
            a[mt][1] = *(const unsigned*)(base + (g + 8) * XPAD);
            a[mt][2] = *(const unsigned*)(base + g * XPAD + 8);
            a[mt][3] = *(const unsigned*)(base + (g + 8) * XPAD + 8);
        }
#pragma unroll
        for (int nt = 0; nt < 8; nt++) {
            const __half* base = ww + (nt * 8 + g) * XPAD + kb + tg * 2;
            b[nt][0] = *(const unsigned*)(base);
            b[nt][1] = *(const unsigned*)(base + 8);
        }
#pragma unroll
        for (int mt = 0; mt < 2; mt++)
#pragma unroll
            for (int nt = 0; nt < 8; nt++)
                mma16816(acc[mt][nt], a[mt], b[nt]);
    }

    // ---- store h16 (half2 per fragment row) ----
#pragma unroll
    for (int mt = 0; mt < 2; mt++) {
        int r0 = row0 + wm * 32 + mt * 16 + g;
        int r1 = r0 + 8;
#pragma unroll
        for (int nt = 0; nt < 8; nt++) {
            int col = wn * 64 + nt * 8 + tg * 2;
            if (r0 < nrows) {
                __half2 p = __floats2half2_rn(acc[mt][nt][0], acc[mt][nt][1]);
                *(__half2*)(g_h16 + (size_t)r0 * F + col) = p;
            }
            if (r1 < nrows) {
                __half2 p = __floats2half2_rn(acc[mt][nt][2], acc[mt][nt][3]);
                *(__half2*)(g_h16 + (size_t)r1 * F + col) = p;
            }
        }
    }

    // ---- fused attention logits (fp32). Warp's 64 cols = heads wn*2, wn*2+1 ----
    float asv[16], adv[16];
#pragma unroll
    for (int nt = 0; nt < 8; nt++) {
        int col = wn * 64 + nt * 8 + tg * 2;
        asv[nt * 2 + 0] = a_src[col];     asv[nt * 2 + 1] = a_src[col + 1];
        adv[nt * 2 + 0] = a_dst[col];     adv[nt * 2 + 1] = a_dst[col + 1];
    }
#pragma unroll
    for (int mt = 0; mt < 2; mt++) {
#pragma unroll
        for (int rp = 0; rp < 2; rp++) {
            int r = row0 + wm * 32 + mt * 16 + rp * 8 + g;
#pragma unroll
            for (int hh = 0; hh < 2; hh++) {
                float ps = 0.f, pd = 0.f;
#pragma unroll
                for (int nt = hh * 4; nt < hh * 4 + 4; nt++) {
                    ps += acc[mt][nt][rp * 2] * asv[nt * 2]
                        + acc[mt][nt][rp * 2 + 1] * asv[nt * 2 + 1];
                    pd += acc[mt][nt][rp * 2] * adv[nt * 2]
                        + acc[mt][nt][rp * 2 + 1] * adv[nt * 2 + 1];
                }
                ps += __shfl_xor_sync(0xffffffffu, ps, 1);
                ps += __shfl_xor_sync(0xffffffffu, ps, 2);
                pd += __shfl_xor_sync(0xffffffffu, pd, 1);
                pd += __shfl_xor_sync(0xffffffffu, pd, 2);
                if (tg == 0 && r < nrows) {
                    int head = wn * 2 + hh;
                    g_als[r * 4 + head] = ps;
                    g_ald[r * 4 + head] = pd;
                }
            }
        }
    }
}

// ---------------- fused GAT aggregation: SINGLE PASS, index-chain pipelined -----
// w_j = exp(e_j) unnormalized; divide by sum at the end. 16 lanes x 16B per edge
// row, two edge streams per warp. csr indices AND their als values for iteration
// i+1 are prefetched during iteration i, so the 2-level csr->h dependency chain
// is broken: h-loads issue at body start. Stale prefetches are in-range -> safe.
__global__ __launch_bounds__(256) void gat_aggr(const float* __restrict__ bias, int nrows)
{
    int gw = (blockIdx.x * blockDim.x + threadIdx.x) >> 5;
    int lane = threadIdx.x & 31;
    if (gw >= nrows) return;

    const int beg = g_rowptr[gw];
    const int end = g_rowptr[gw + 1];

    const int half = lane >> 4;          // 0: even edges, 1: odd edges
    const int sub = lane & 15;           // feature group: sub*8 .. sub*8+7
    const int head = sub >> 2;
    const float aldh = g_ald[gw * 4 + head];

    float acc[8];
#pragma unroll
    for (int c = 0; c < 8; c++) acc[c] = 0.f;
    float s = 0.f;

    int j = beg + half;
    // prologue: prefetch indices + logits for the first iteration
    int s0n = (j < end) ? g_csr_src[j] : 0;
    int s1n = (j + 2 < end) ? g_csr_src[j + 2] : 0;
    float a0n = g_als[s0n * 4 + head];
    float a1n = g_als[s1n * 4 + head];

    for (; j + 2 < end; j += 4) {
        const int s0 = s0n, s1 = s1n;
        const float a0 = a0n, a1 = a1n;
        // h-loads issue immediately (indices known since last iteration)
        uint4 r0 = *(const uint4*)(g_h16 + (size_t)s0 * F + sub * 8);
        uint4 r1 = *(const uint4*)(g_h16 + (size_t)s1 * F + sub * 8);
        // prefetch next iteration's indices + logits (stale values stay in range)
        int jn = j + 4;
        if (jn < end)     s0n = g_csr_src[jn];
        if (jn + 2 < end) s1n = g_csr_src[jn + 2];
        a0n = g_als[s0n * 4 + head];
        a1n = g_als[s1n * 4 + head];

        float w0 = __expf(lrelu(a0 + aldh));
        float w1 = __expf(lrelu(a1 + aldh));
        s += w0 + w1;
        const __half2* p0 = (const __half2*)&r0;
        const __half2* p1 = (const __half2*)&r1;
#pragma unroll
        for (int c = 0; c < 4; c++) {
            float2 f0 = __half22float2(p0[c]);
            float2 f1 = __half22float2(p1[c]);
            acc[c * 2 + 0] += w0 * f0.x + w1 * f1.x;
            acc[c * 2 + 1] += w0 * f0.y + w1 * f1.y;
        }
    }
    if (j < end) {          // tail: s0n/a0n hold csr[j]/als for it
        float w0 = __expf(lrelu(a0n + aldh));
        uint4 r0 = *(const uint4*)(g_h16 + (size_t)s0n * F + sub * 8);
        s += w0;
        const __half2* p0 = (const __half2*)&r0;
#pragma unroll
        for (int c = 0; c < 4; c++) {
            float2 f0 = __half22float2(p0[c]);
            acc[c * 2 + 0] += w0 * f0.x;
            acc[c * 2 + 1] += w0 * f0.y;
        }
    }

    // combine the two edge streams
    s += __shfl_xor_sync(0xffffffffu, s, 16);
#pragma unroll
    for (int c = 0; c < 8; c++)
        acc[c] += __shfl_xor_sync(0xffffffffu, acc[c], 16);

    if (half == 0) {
        float inv = 1.f / (s + 1e-16f);
        float4 b0 = *(const float4*)(bias + sub * 8);
        float4 b1 = *(const float4*)(bias + sub * 8 + 4);
        acc[0] = acc[0] * inv + b0.x; acc[1] = acc[1] * inv + b0.y;
        acc[2] = acc[2] * inv + b0.z; acc[3] = acc[3] * inv + b0.w;
        acc[4] = acc[4] * inv + b1.x; acc[5] = acc[5] * inv + b1.y;
        acc[6] = acc[6] * inv + b1.z; acc[7] = acc[7] * inv + b1.w;
#pragma unroll
        for (int c = 0; c < 8; c++)
            acc[c] = acc[c] > 0.f ? acc[c] : expm1f(acc[c]);
        __half2 hp[4];
        hp[0] = __floats2half2_rn(acc[0], acc[1]);
        hp[1] = __floats2half2_rn(acc[2], acc[3]);
        hp[2] = __floats2half2_rn(acc[4], acc[5]);
        hp[3] = __floats2half2_rn(acc[6], acc[7]);
        *(uint4*)(g_out16 + (size_t)gw * F + sub * 8) = *(uint4*)hp;
    }
}

// ---------------- FC (128->10) + log_softmax; one warp per node ----------------
__global__ __launch_bounds__(256) void fc_logsoftmax(
    const float* __restrict__ fcW, const float* __restrict__ fcb,
    float* __restrict__ out, int nrows)
{
    __shared__ float wsm[128 * 10];
    __shared__ float bsm[10];
    int tid = threadIdx.x;
    for (int i = tid; i < 1280; i += blockDim.x) wsm[i] = fcW[i];
    if (tid < 10) bsm[tid] = fcb[tid];
    __syncthreads();

    int gw = (blockIdx.x * blockDim.x + tid) >> 5;
    int lane = tid & 31;
    if (gw >= nrows) return;

    uint2 rv = *(const uint2*)(g_out16 + (size_t)gw * F + lane * 4);
    float2 lo = __half22float2(*(__half2*)&rv.x);
    float2 hi = __half22float2(*(__half2*)&rv.y);
    float acc[10];
#pragma unroll
    for (int c = 0; c < 10; c++) {
        acc[c] = lo.x * wsm[(lane * 4 + 0) * 10 + c]
               + lo.y * wsm[(lane * 4 + 1) * 10 + c]
               + hi.x * wsm[(lane * 4 + 2) * 10 + c]
               + hi.y * wsm[(lane * 4 + 3) * 10 + c];
    }
#pragma unroll
    for (int off = 16; off; off >>= 1)
#pragma unroll
        for (int c = 0; c < 10; c++)
            acc[c] += __shfl_xor_sync(0xffffffffu, acc[c], off);

    if (lane == 0) {
        float mx = -FLT_MAX;
#pragma unroll
        for (int c = 0; c < 10; c++) { acc[c] += bsm[c]; mx = fmaxf(mx, acc[c]); }
        float ssum = 0.f;
#pragma unroll
        for (int c = 0; c < 10; c++) ssum += expf(acc[c] - mx);
        float lse = mx + logf(ssum);
#pragma unroll
        for (int c = 0; c < 10; c++) out[(size_t)gw * 10 + c] = acc[c] - lse;
    }
}

// ---------------- host launcher ----------------
extern "C" void kernel_launch(void* const* d_in, const int* in_sizes, int n_in,
                              void* d_out, int out_size)
{
    const float* x   = (const float*)d_in[0];
    const int*   ei  = (const int*)d_in[1];
    const int E = in_sizes[1] / 2;

    const float* W[3]  = {(const float*)d_in[2], (const float*)d_in[6],  (const float*)d_in[10]};
    const float* As[3] = {(const float*)d_in[3], (const float*)d_in[7],  (const float*)d_in[11]};
    const float* Ad[3] = {(const float*)d_in[4], (const float*)d_in[8],  (const float*)d_in[12]};
    const float* B[3]  = {(const float*)d_in[5], (const float*)d_in[9],  (const float*)d_in[13]};
    const float* fcW = (const float*)d_in[14];
    const float* fcb = (const float*)d_in[15];
    float* out = (float*)d_out;

    __half* p_out16 = nullptr;
    cudaGetSymbolAddress((void**)&p_out16, g_out16);
    __half* p_wt = nullptr;
    cudaGetSymbolAddress((void**)&p_wt, g_wt16);

    const int SMEM_GEMM = 2 * 128 * XPAD * (int)sizeof(__half);   // 69632 B
    cudaFuncSetAttribute(gemm_mma<float>, cudaFuncAttributeMaxDynamicSharedMemorySize, SMEM_GEMM);
    cudaFuncSetAttribute(gemm_mma<__half>, cudaFuncAttributeMaxDynamicSharedMemorySize, SMEM_GEMM);

    const int gemm_blocks  = (NN + 127) / 128;            // 782
    const int nodeW_blocks = (NN * 32 + 255) / 256;
    const int scan_blocks  = (NN + 1023) / 1024;          // 98
    const int hblocks      = (E + 1023) / 1024;           // 4 edges/thread
    const int wblocks      = (3 * F * F + 255) / 256;     // 192
    const int loop_blocks  = (NN + 255) / 256;            // self-loop scatter

    // launch 1: W conversion + dst histogram (real edges only)
    csr_hist_wconv<<<hblocks + wblocks, 256>>>(ei, E, hblocks, W[0], W[1], W[2]);
    // launch 2-3: scan (adds +1 self loop analytically)
    csr_scanA<<<scan_blocks, 1024>>>(NN);
    csr_scanB<<<scan_blocks, 1024>>>(NN, 0);
    // launch 4: GEMM layer 0 (independent of CSR; ncu profiles launch #4)
    gemm_mma<float><<<gemm_blocks, 256, SMEM_GEMM>>>(x, p_wt, As[0], Ad[0], NN);
    // launch 5: scatter (real edges + self loops)
    csr_scatter<<<hblocks + loop_blocks, 256>>>(ei, E, hblocks);
    // launch 6+: aggregation + remaining layers
    gat_aggr<<<nodeW_blocks, 256>>>(B[0], NN);
    for (int l = 1; l < 3; l++) {
        gemm_mma<__half><<<gemm_blocks, 256, SMEM_GEMM>>>(p_out16, p_wt + (size_t)l * F * F,
                                                          As[l], Ad[l], NN);
        gat_aggr<<<nodeW_blocks, 256>>>(B[l], NN);
    }
    fc_logsoftmax<<<nodeW_blocks, 256>>>(fcW, fcb, out, NN);
}

// round 17
// speedup vs baseline: 1.0377x; 1.0377x over previous
#include <cuda_runtime.h>
#include <cuda_fp16.h>
#include <math.h>
#include <float.h>

#define NN 100000
#define F 128          // HEADS*NHID
#define EMAX 1700000   // 1.6M edges + 100k self loops

// ---------------- scratch (device globals; no allocation allowed) ----------------
__device__ __half g_h16[(size_t)NN * F];   // h = x @ W, fp16 (gather payload)
__device__ __half g_out16[(size_t)NN * F]; // activated layer output, fp16
__device__ float g_als[NN * 4];            // alpha logits (src side), per head
__device__ float g_ald[NN * 4];            // alpha logits (dst side), per head
__device__ __half g_wt16[3][F * F];        // W^T in fp16, per layer

// CSR build scratch (g_deg zero at module load; csr_alloc re-zeros it each run;
// g_cursor reset by launch 1 each run)
__device__ int g_deg[NN];                  // real-edge degree (self-loop added in alloc)
__device__ int g_cursor;                   // bump allocator for row segments
__device__ int2 g_rowspan[NN];             // (beg, end) of each node's edge segment
__device__ int g_wptr[NN];
__device__ int g_csr_src[EMAX];

// ---------------- helpers ----------------
__device__ __forceinline__ float lrelu(float v) { return v > 0.f ? v : 0.2f * v; }

__device__ __forceinline__ void mma16816(float* d, const unsigned* a, const unsigned* b)
{
    asm volatile(
        "mma.sync.aligned.m16n8k16.row.col.f32.f16.f16.f32 "
        "{%0,%1,%2,%3}, {%4,%5,%6,%7}, {%8,%9}, {%0,%1,%2,%3};"
        : "+f"(d[0]), "+f"(d[1]), "+f"(d[2]), "+f"(d[3])
        : "r"(a[0]), "r"(a[1]), "r"(a[2]), "r"(a[3]), "r"(b[0]), "r"(b[1]));
}

// ---------------- launch 1: fused W-transpose-to-fp16 + edge histogram ----------
__global__ __launch_bounds__(256) void csr_hist_wconv(
    const int* __restrict__ ei, int E, int hblocks,
    const float* __restrict__ W0, const float* __restrict__ W1,
    const float* __restrict__ W2)
{
    int b = blockIdx.x;
    if (b < hblocks) {
        int i = (b * 256 + threadIdx.x) * 4;
        if (((E & 3) == 0) && i + 3 < E) {
            int4 d4 = *(const int4*)(ei + E + i);
            atomicAdd(&g_deg[d4.x], 1);
            atomicAdd(&g_deg[d4.y], 1);
            atomicAdd(&g_deg[d4.z], 1);
            atomicAdd(&g_deg[d4.w], 1);
        } else {
#pragma unroll
            for (int k = 0; k < 4; k++)
                if (i + k < E) atomicAdd(&g_deg[ei[E + i + k]], 1);
        }
    } else {
        int i = (b - hblocks) * 256 + threadIdx.x;      // 0 .. 3*16384-1
        if (i == 0) g_cursor = 0;                       // reset bump allocator
        if (i >= 3 * F * F) return;
        int l = i >> 14;
        int r = i & (F * F - 1);
        int n = r >> 7;
        int k = r & 127;
        const float* W = (l == 0) ? W0 : ((l == 1) ? W1 : W2);
        g_wt16[l][n * F + k] = __float2half(W[k * F + n]);
    }
}

// ---------------- launch 2: per-row segment allocation (replaces both scans) ----
// Warp prefix-sum of (deg+1), ONE atomicAdd per warp on the global cursor.
// Rows land in arbitrary order — irrelevant, only per-row contiguity matters.
__global__ __launch_bounds__(256) void csr_alloc(int n)
{
    int i = blockIdx.x * blockDim.x + threadIdx.x;
    int lane = threadIdx.x & 31;
    int d = (i < n) ? (g_deg[i] + 1) : 0;     // +1: self loop
    int pref = d;
#pragma unroll
    for (int off = 1; off < 32; off <<= 1) {
        int t = __shfl_up_sync(0xffffffffu, pref, off);
        if (lane >= off) pref += t;
    }
    int base = 0;
    if (lane == 31) base = atomicAdd(&g_cursor, pref);  // pref@31 = warp total
    base = __shfl_sync(0xffffffffu, base, 31);
    if (i < n) {
        int beg = base + pref - d;
        g_rowspan[i] = make_int2(beg, beg + d);
        g_wptr[i] = beg;
        g_deg[i] = 0;                        // reset for the next replay
    }
}

// ---------------- launch 4: scatter (4 real edges/thread + self-loop range) -----
__global__ __launch_bounds__(256) void csr_scatter(const int* __restrict__ ei,
                                                   int E, int sblocks)
{
    int b = blockIdx.x;
    if (b < sblocks) {
        int i = (b * 256 + threadIdx.x) * 4;
        if (((E & 3) == 0) && i + 3 < E) {
            int4 s4 = *(const int4*)(ei + i);
            int4 d4 = *(const int4*)(ei + E + i);
            int p0 = atomicAdd(&g_wptr[d4.x], 1);
            int p1 = atomicAdd(&g_wptr[d4.y], 1);
            int p2 = atomicAdd(&g_wptr[d4.z], 1);
            int p3 = atomicAdd(&g_wptr[d4.w], 1);
            g_csr_src[p0] = s4.x;
            g_csr_src[p1] = s4.y;
            g_csr_src[p2] = s4.z;
            g_csr_src[p3] = s4.w;
        } else {
#pragma unroll
            for (int k = 0; k < 4; k++)
                if (i + k < E) {
                    int s = ei[i + k], d = ei[E + i + k];
                    int pos = atomicAdd(&g_wptr[d], 1);
                    g_csr_src[pos] = s;
                }
        }
    } else {
        int i = (b - sblocks) * 256 + threadIdx.x;   // self loops
        if (i < NN) {
            int pos = atomicAdd(&g_wptr[i], 1);
            g_csr_src[pos] = i;
        }
    }
}

// ---------------- X-tile loaders (fp32 layer0 / fp16 layers 1-2), 256 threads ----
#define XPAD 136   // 128 + 8 halves padding
__device__ __forceinline__ void load_xtile(
    const float* __restrict__ X, __half* xs, int tid, int row0, int nrows)
{
#pragma unroll
    for (int i = 0; i < 16; i++) {
        int f = tid + i * 256;               // float4 index: 128 rows x 32
        int r = f >> 5, c4 = (f & 31) << 2;
        float4 v = make_float4(0.f, 0.f, 0.f, 0.f);
        if (row0 + r < nrows) v = *(const float4*)(X + (size_t)(row0 + r) * F + c4);
        __half2 p0 = __floats2half2_rn(v.x, v.y);
        __half2 p1 = __floats2half2_rn(v.z, v.w);
        uint2 u;
        u.x = *(unsigned*)&p0; u.y = *(unsigned*)&p1;
        *(uint2*)(xs + r * XPAD + c4) = u;
    }
}

__device__ __forceinline__ void load_xtile(
    const __half* __restrict__ X, __half* xs, int tid, int row0, int nrows)
{
#pragma unroll
    for (int i = 0; i < 8; i++) {
        int f = tid + i * 256;               // uint4 index: 128 rows x 16
        int r = f >> 4, c = (f & 15) << 3;
        uint4 u = make_uint4(0u, 0u, 0u, 0u);
        if (row0 + r < nrows) u = *(const uint4*)(X + (size_t)(row0 + r) * F + c);
        *(uint4*)(xs + r * XPAD + c) = u;
    }
}

// ---------------- launch 3: HMMA GEMM + fused attention-logit epilogue ----------
// R14 configuration (measured 27.9-28.2us): 128x128 tile, 256 threads = 4(m)x2(n).
template <typename T>
__global__ __launch_bounds__(256) void gemm_mma(
    const T* __restrict__ X, const __half* __restrict__ WT,
    const float* __restrict__ a_src, const float* __restrict__ a_dst, int nrows)
{
    extern __shared__ __half sh[];
    __half* xs = sh;                 // [128][XPAD]  row-major (m,k)
    __half* ws = sh + 128 * XPAD;    // [128][XPAD]  n-major  (n,k)

    const int tid = threadIdx.x;
    const int warp = tid >> 5, lane = tid & 31;
    const int g = lane >> 2, tg = lane & 3;
    const int wm = warp & 3, wn = warp >> 2;     // 4 m-warps x 2 n-warps
    const int row0 = blockIdx.x * 128;

    load_xtile(X, xs, tid, row0, nrows);
#pragma unroll
    for (int i = 0; i < 8; i++) {
        int f = tid + i * 256;               // uint4 index: 128 rows x 16
        int n = f >> 4, kw = (f & 15) << 3;
        *(uint4*)(ws + n * XPAD + kw) = *(const uint4*)(WT + n * F + kw);
    }
    __syncthreads();

    float acc[2][8][4];
#pragma unroll
    for (int mt = 0; mt < 2; mt++)
#pragma unroll
        for (int nt = 0; nt < 8; nt++)
#pragma unroll
            for (int c = 0; c < 4; c++) acc[mt][nt][c] = 0.f;

    const __half* xw = xs + (wm * 32) * XPAD;
    const __half* ww = ws + (wn * 64) * XPAD;

#pragma unroll
    for (int kt = 0; kt < 8; kt++) {
        const int kb = kt * 16;
        unsigned a[2][4], b[8][2];
#pragma unroll
        for (int mt = 0; mt < 2; mt++) {
            const __half* base = xw + (mt * 16) * XPAD + kb + tg * 2;
            a[mt][0] = *(const unsigned*)(base + g * XPAD);
            a[mt][1] = *(const unsigned*)(base + (g + 8) * XPAD);
            a[mt][2] = *(const unsigned*)(base + g * XPAD + 8);
            a[mt][3] = *(const unsigned*)(base + (g + 8) * XPAD + 8);
        }
#pragma unroll
        for (int nt = 0; nt < 8; nt++) {
            const __half* base = ww + (nt * 8 + g) * XPAD + kb + tg * 2;
            b[nt][0] = *(const unsigned*)(base);
            b[nt][1] = *(const unsigned*)(base + 8);
        }
#pragma unroll
        for (int mt = 0; mt < 2; mt++)
#pragma unroll
            for (int nt = 0; nt < 8; nt++)
                mma16816(acc[mt][nt], a[mt], b[nt]);
    }

    // ---- store h16 (half2 per fragment row) ----
#pragma unroll
    for (int mt = 0; mt < 2; mt++) {
        int r0 = row0 + wm * 32 + mt * 16 + g;
        int r1 = r0 + 8;
#pragma unroll
        for (int nt = 0; nt < 8; nt++) {
            int col = wn * 64 + nt * 8 + tg * 2;
            if (r0 < nrows) {
                __half2 p = __floats2half2_rn(acc[mt][nt][0], acc[mt][nt][1]);
                *(__half2*)(g_h16 + (size_t)r0 * F + col) = p;
            }
            if (r1 < nrows) {
                __half2 p = __floats2half2_rn(acc[mt][nt][2], acc[mt][nt][3]);
                *(__half2*)(g_h16 + (size_t)r1 * F + col) = p;
            }
        }
    }

    // ---- fused attention logits (fp32). Warp's 64 cols = heads wn*2, wn*2+1 ----
    float asv[16], adv[16];
#pragma unroll
    for (int nt = 0; nt < 8; nt++) {
        int col = wn * 64 + nt * 8 + tg * 2;
        asv[nt * 2 + 0] = a_src[col];     asv[nt * 2 + 1] = a_src[col + 1];
        adv[nt * 2 + 0] = a_dst[col];     adv[nt * 2 + 1] = a_dst[col + 1];
    }
#pragma unroll
    for (int mt = 0; mt < 2; mt++) {
#pragma unroll
        for (int rp = 0; rp < 2; rp++) {
            int r = row0 + wm * 32 + mt * 16 + rp * 8 + g;
#pragma unroll
            for (int hh = 0; hh < 2; hh++) {
                float ps = 0.f, pd = 0.f;
#pragma unroll
                for (int nt = hh * 4; nt < hh * 4 + 4; nt++) {
                    ps += acc[mt][nt][rp * 2] * asv[nt * 2]
                        + acc[mt][nt][rp * 2 + 1] * asv[nt * 2 + 1];
                    pd += acc[mt][nt][rp * 2] * adv[nt * 2]
                        + acc[mt][nt][rp * 2 + 1] * adv[nt * 2 + 1];
                }
                ps += __shfl_xor_sync(0xffffffffu, ps, 1);
                ps += __shfl_xor_sync(0xffffffffu, ps, 2);
                pd += __shfl_xor_sync(0xffffffffu, pd, 1);
                pd += __shfl_xor_sync(0xffffffffu, pd, 2);
                if (tg == 0 && r < nrows) {
                    int head = wn * 2 + hh;
                    g_als[r * 4 + head] = ps;
                    g_ald[r * 4 + head] = pd;
                }
            }
        }
    }
}

// ---------------- fused GAT aggregation: SINGLE PASS (exact R13 loop form) ------
// w_j = exp(e_j) unnormalized (|e| small, exp safe); divide by sum at the end.
// 16 lanes x 16B per edge row; two edge streams per warp (lane halves).
__global__ __launch_bounds__(256) void gat_aggr(const float* __restrict__ bias, int nrows)
{
    int gw = (blockIdx.x * blockDim.x + threadIdx.x) >> 5;
    int lane = threadIdx.x & 31;
    if (gw >= nrows) return;

    const int2 span = g_rowspan[gw];
    const int beg = span.x;
    const int end = span.y;

    const int half = lane >> 4;          // 0: even edges, 1: odd edges
    const int sub = lane & 15;           // feature group: sub*8 .. sub*8+7
    const int head = sub >> 2;
    const float aldh = g_ald[gw * 4 + head];

    float acc[8];
#pragma unroll
    for (int c = 0; c < 8; c++) acc[c] = 0.f;
    float s = 0.f;

    int j = beg + half;
    for (; j + 2 < end; j += 4) {        // unroll 2: edges j and j+2
        int s0 = g_csr_src[j];
        int s1 = g_csr_src[j + 2];
        float a0 = g_als[s0 * 4 + head];
        float a1 = g_als[s1 * 4 + head];
        uint4 r0 = *(const uint4*)(g_h16 + (size_t)s0 * F + sub * 8);
        uint4 r1 = *(const uint4*)(g_h16 + (size_t)s1 * F + sub * 8);
        float w0 = __expf(lrelu(a0 + aldh));
        float w1 = __expf(lrelu(a1 + aldh));
        s += w0 + w1;
        const __half2* p0 = (const __half2*)&r0;
        const __half2* p1 = (const __half2*)&r1;
#pragma unroll
        for (int c = 0; c < 4; c++) {
            float2 f0 = __half22float2(p0[c]);
            float2 f1 = __half22float2(p1[c]);
            acc[c * 2 + 0] += w0 * f0.x + w1 * f1.x;
            acc[c * 2 + 1] += w0 * f0.y + w1 * f1.y;
        }
    }
    if (j < end) {
        int s0 = g_csr_src[j];
        float w0 = __expf(lrelu(g_als[s0 * 4 + head] + aldh));
        uint4 r0 = *(const uint4*)(g_h16 + (size_t)s0 * F + sub * 8);
        s += w0;
        const __half2* p0 = (const __half2*)&r0;
#pragma unroll
        for (int c = 0; c < 4; c++) {
            float2 f0 = __half22float2(p0[c]);
            acc[c * 2 + 0] += w0 * f0.x;
            acc[c * 2 + 1] += w0 * f0.y;
        }
    }

    // combine the two edge streams
    s += __shfl_xor_sync(0xffffffffu, s, 16);
#pragma unroll
    for (int c = 0; c < 8; c++)
        acc[c] += __shfl_xor_sync(0xffffffffu, acc[c], 16);

    if (half == 0) {
        float inv = 1.f / (s + 1e-16f);
        float4 b0 = *(const float4*)(bias + sub * 8);
        float4 b1 = *(const float4*)(bias + sub * 8 + 4);
        acc[0] = acc[0] * inv + b0.x; acc[1] = acc[1] * inv + b0.y;
        acc[2] = acc[2] * inv + b0.z; acc[3] = acc[3] * inv + b0.w;
        acc[4] = acc[4] * inv + b1.x; acc[5] = acc[5] * inv + b1.y;
        acc[6] = acc[6] * inv + b1.z; acc[7] = acc[7] * inv + b1.w;
#pragma unroll
        for (int c = 0; c < 8; c++)
            acc[c] = acc[c] > 0.f ? acc[c] : expm1f(acc[c]);
        __half2 hp[4];
        hp[0] = __floats2half2_rn(acc[0], acc[1]);
        hp[1] = __floats2half2_rn(acc[2], acc[3]);
        hp[2] = __floats2half2_rn(acc[4], acc[5]);
        hp[3] = __floats2half2_rn(acc[6], acc[7]);
        *(uint4*)(g_out16 + (size_t)gw * F + sub * 8) = *(uint4*)hp;
    }
}

// ---------------- FC (128->10) + log_softmax; one warp per node ----------------
__global__ __launch_bounds__(256) void fc_logsoftmax(
    const float* __restrict__ fcW, const float* __restrict__ fcb,
    float* __restrict__ out, int nrows)
{
    __shared__ float wsm[128 * 10];
    __shared__ float bsm[10];
    int tid = threadIdx.x;
    for (int i = tid; i < 1280; i += blockDim.x) wsm[i] = fcW[i];
    if (tid < 10) bsm[tid] = fcb[tid];
    __syncthreads();

    int gw = (blockIdx.x * blockDim.x + tid) >> 5;
    int lane = tid & 31;
    if (gw >= nrows) return;

    uint2 rv = *(const uint2*)(g_out16 + (size_t)gw * F + lane * 4);
    float2 lo = __half22float2(*(__half2*)&rv.x);
    float2 hi = __half22float2(*(__half2*)&rv.y);
    float acc[10];
#pragma unroll
    for (int c = 0; c < 10; c++) {
        acc[c] = lo.x * wsm[(lane * 4 + 0) * 10 + c]
               + lo.y * wsm[(lane * 4 + 1) * 10 + c]
               + hi.x * wsm[(lane * 4 + 2) * 10 + c]
               + hi.y * wsm[(lane * 4 + 3) * 10 + c];
    }
#pragma unroll
    for (int off = 16; off; off >>= 1)
#pragma unroll
        for (int c = 0; c < 10; c++)
            acc[c] += __shfl_xor_sync(0xffffffffu, acc[c], off);

    if (lane == 0) {
        float mx = -FLT_MAX;
#pragma unroll
        for (int c = 0; c < 10; c++) { acc[c] += bsm[c]; mx = fmaxf(mx, acc[c]); }
        float ssum = 0.f;
#pragma unroll
        for (int c = 0; c < 10; c++) ssum += expf(acc[c] - mx);
        float lse = mx + logf(ssum);
#pragma unroll
        for (int c = 0; c < 10; c++) out[(size_t)gw * 10 + c] = acc[c] - lse;
    }
}

// ---------------- host launcher ----------------
extern "C" void kernel_launch(void* const* d_in, const int* in_sizes, int n_in,
                              void* d_out, int out_size)
{
    const float* x   = (const float*)d_in[0];
    const int*   ei  = (const int*)d_in[1];
    const int E = in_sizes[1] / 2;

    const float* W[3]  = {(const float*)d_in[2], (const float*)d_in[6],  (const float*)d_in[10]};
    const float* As[3] = {(const float*)d_in[3], (const float*)d_in[7],  (const float*)d_in[11]};
    const float* Ad[3] = {(const float*)d_in[4], (const float*)d_in[8],  (const float*)d_in[12]};
    const float* B[3]  = {(const float*)d_in[5], (const float*)d_in[9],  (const float*)d_in[13]};
    const float* fcW = (const float*)d_in[14];
    const float* fcb = (const float*)d_in[15];
    float* out = (float*)d_out;

    __half* p_out16 = nullptr;
    cudaGetSymbolAddress((void**)&p_out16, g_out16);
    __half* p_wt = nullptr;
    cudaGetSymbolAddress((void**)&p_wt, g_wt16);

    const int SMEM_GEMM = 2 * 128 * XPAD * (int)sizeof(__half);   // 69632 B
    cudaFuncSetAttribute(gemm_mma<float>, cudaFuncAttributeMaxDynamicSharedMemorySize, SMEM_GEMM);
    cudaFuncSetAttribute(gemm_mma<__half>, cudaFuncAttributeMaxDynamicSharedMemorySize, SMEM_GEMM);

    const int gemm_blocks  = (NN + 127) / 128;            // 782
    const int nodeW_blocks = (NN * 32 + 255) / 256;
    const int nodeT_blocks = (NN + 255) / 256;            // alloc / self-loop
    const int hblocks      = (E + 1023) / 1024;           // 4 edges/thread
    const int wblocks      = (3 * F * F + 255) / 256;     // 192

    // launch 1: W conversion + dst histogram + cursor reset
    csr_hist_wconv<<<hblocks + wblocks, 256>>>(ei, E, hblocks, W[0], W[1], W[2]);
    // launch 2: per-row segment allocation (replaces scanA + scanB)
    csr_alloc<<<nodeT_blocks, 256>>>(NN);
    // launch 3: GEMM layer 0 (independent of scatter)
    gemm_mma<float><<<gemm_blocks, 256, SMEM_GEMM>>>(x, p_wt, As[0], Ad[0], NN);
    // launch 4: scatter (real edges + self loops) — profiled slot
    csr_scatter<<<hblocks + nodeT_blocks, 256>>>(ei, E, hblocks);
    // launch 5+: aggregation + remaining layers
    gat_aggr<<<nodeW_blocks, 256>>>(B[0], NN);
    for (int l = 1; l < 3; l++) {
        gemm_mma<__half><<<gemm_blocks, 256, SMEM_GEMM>>>(p_out16, p_wt + (size_t)l * F * F,
                                                          As[l], Ad[l], NN);
        gat_aggr<<<nodeW_blocks, 256>>>(B[l], NN);
    }
    fc_logsoftmax<<<nodeW_blocks, 256>>>(fcW, fcb, out, NN);
}